// round 13
// baseline (speedup 1.0000x reference)
#include <cuda_runtime.h>
#include <stdint.h>

// ---------------- constants ----------------
#define MAXN_LAB  (1 << 18)          // label scratch capacity (N = 200000 fits)
#define MAXC_FAST 108                // fast path: C*256*4 <= ~110KB (2 blocks/SM)
#define ENC_NINF  ((int)0x807FFFFF)  // order-preserving encoding of -inf
#define F_NINF    __int_as_float(0xff800000)

// ---------------- device scratch (static: no allocation) ----------------
__device__ int g_off[MAXN_LAB + 16];   // pre-scaled smem byte offsets: label*1024
__device__ int g_is64;

// Order-preserving float<->int bijection (self-inverse, monotone for non-NaN).
__device__ __forceinline__ int enc_f(float f) {
    int i = __float_as_int(f);
    return (i >= 0) ? i : (i ^ 0x7fffffff);
}

// ---------------- kernel 0: init output + sampled width detect ------------
// int64 labels in [0,C) have every odd int32 word == 0 (little endian).
// Threads gid < lim each test ONE odd word (word 2*gid+1). If the buffer is
// really int32, word 2*gid+1 is label #(2*gid+1): in-bounds (2*gid+1 < N)
// and nonzero w.h.p. P(10k consecutive labels all zero) ~ (1/C)^10k ~ 0.
// No loops, no serial block: ~1 load per thread.
__global__ void smp_init(int* __restrict__ out_enc, int BC,
                         const int* __restrict__ l32, int N) {
    int gid = blockIdx.x * blockDim.x + threadIdx.x;
    if (gid == 0) g_is64 = 1;
    if (gid < BC) out_enc[gid] = ENC_NINF;
    int lim = (N - 1) >> 1;                 // 2*gid+1 < N  -> int32-safe
    if (lim > 10000) lim = 10000;
    if (gid < lim && l32[2 * gid + 1] != 0)
        g_is64 = 0;                          // racy same-value store: fine
}

// ---------------- kernel 1: compact labels -> pre-scaled byte offsets -----
// offset = c * 1024  (acc stride per class = 256 threads * 4B)
__global__ void smp_compact(const void* __restrict__ labels, int N) {
    int i = blockIdx.x * blockDim.x + threadIdx.x;
    if (i < N) {
        int v = g_is64 ? (int)((const long long*)labels)[i]
                       : ((const int*)labels)[i];
        g_off[i] = v << 10;
    }
}

// ---------------- kernel 2: main streaming max ----------------------------
// Grid (slices, ceil(B/8)), 256 threads (8 warps; warp w owns one row).
// Lane-private accumulators acc[c*256 + tid]:
//   - bank = lane for every access -> conflict-free for ANY label pattern
//   - single owner -> no races, no atomics, no branches in the hot loop
// Hot loop per lane-quad (round-5 proven RMW body) with a DEPTH-2 load
// pipeline: two iterations of value+offset loads outstanding (~2KB/warp in
// flight) while exactly one smem RMW phase runs per iteration.
//   - batched LDS x4 of stale cells (one latency window per 4 elements)
//   - branchless duplicate forward-propagation makes batched stale reads
//     exact (last store to a duplicated address carries the running max)
// Merge: warp shfl-max per class + one global atomicMax per (warp, class).
__global__ __launch_bounds__(256, 2) void smp_main(
    const float* __restrict__ vals, int* __restrict__ out_enc,
    int B, int N, int C, int JW)
{
    extern __shared__ float acc[];          // [C][256]
    const int tid  = threadIdx.x;
    const int w    = tid >> 5;
    const int lane = tid & 31;
    const int row  = blockIdx.y * 8 + w;
    const int j0   = blockIdx.x * JW;

    // Init private cells. Disjoint ownership: no sync needed.
    #pragma unroll 4
    for (int c = 0; c < C; c++) acc[c * 256 + tid] = F_NINF;

    if (row < B && j0 < N) {
        const int n  = min(JW, N - j0);
        const int n4 = n >> 2;
        const float4* rp = (const float4*)(vals + (size_t)row * N + j0);
        const int4*   op = (const int4*)(g_off + j0);
        char* aB = (char*)acc + (tid << 2);

        int  i    = lane;
        bool has0 = (i < n4);
        bool has1 = (i + 32 < n4);
        float4 v0, v1; int4 o0, o1;
        if (has0) { v0 = __ldcs(rp + i);      o0 = op[i]; }
        if (has1) { v1 = __ldcs(rp + i + 32); o1 = op[i + 32]; }

        while (has0) {
            const int  i2 = i + 64;
            const bool m  = (i2 < n4);
            const int  ip = m ? i2 : i;                // clamped, in-bounds
            float4 v2 = __ldcs(rp + ip);               // prefetch depth 2
            int4   o2 = op[ip];

            // ---- one RMW phase (identical to round-5 winner) ----
            float* a0 = (float*)(aB + o0.x);
            float* a1 = (float*)(aB + o0.y);
            float* a2 = (float*)(aB + o0.z);
            float* a3 = (float*)(aB + o0.w);
            float s0 = *a0, s1 = *a1, s2 = *a2, s3 = *a3;
            if (o0.x == o0.y) v0.y = fmaxf(v0.y, v0.x);
            if (o0.x == o0.z) v0.z = fmaxf(v0.z, v0.x);
            if (o0.y == o0.z) v0.z = fmaxf(v0.z, v0.y);
            if (o0.x == o0.w) v0.w = fmaxf(v0.w, v0.x);
            if (o0.y == o0.w) v0.w = fmaxf(v0.w, v0.y);
            if (o0.z == o0.w) v0.w = fmaxf(v0.w, v0.z);
            *a0 = fmaxf(s0, v0.x);
            *a1 = fmaxf(s1, v0.y);
            *a2 = fmaxf(s2, v0.z);
            *a3 = fmaxf(s3, v0.w);

            v0 = v1; o0 = o1; v1 = v2; o1 = o2;
            has0 = has1; has1 = m; i += 32;
        }
        // Scalar tail (n % 4 != 0).
        const int tail = n & 3;
        if (lane < tail) {
            int col = j0 + (n4 << 2) + lane;
            float x = vals[(size_t)row * N + col];
            float* a = (float*)(aB + g_off[col]);
            *a = fmaxf(*a, x);
        }
    }
    // No __syncthreads needed before merge: each thread reads only its cells.

    if (row < B) {
        int* orow = out_enc + row * C;
        for (int c = 0; c < C; c++) {
            float m = acc[c * 256 + tid];
            #pragma unroll
            for (int off = 16; off; off >>= 1)
                m = fmaxf(m, __shfl_xor_sync(0xffffffffu, m, off));
            if (lane == 0 && m > F_NINF)
                atomicMax(orow + c, enc_f(m));
        }
    }
}

// ---------------- fallback: fully general (C > MAXC_FAST or N > MAXN_LAB) --
__global__ void smp_naive(const float* __restrict__ vals, const void* __restrict__ labels,
                          int* __restrict__ out_enc, int B, int N, int C)
{
    long long total  = (long long)B * N;
    long long stride = (long long)gridDim.x * blockDim.x;
    int is64 = g_is64;
    for (long long idx = blockIdx.x * (long long)blockDim.x + threadIdx.x;
         idx < total; idx += stride) {
        int j = (int)(idx % N);
        int b = (int)(idx / N);
        int c = is64 ? (int)((const long long*)labels)[j]
                     : ((const int*)labels)[j];
        atomicMax(out_enc + b * C + c, enc_f(vals[idx]));
    }
}

// ---------------- kernel 3: decode in place ----------------
__global__ void smp_fin(int* __restrict__ io, int BC) {
    int i = blockIdx.x * blockDim.x + threadIdx.x;
    if (i < BC) {
        int e = io[i];
        io[i] = (e >= 0) ? e : (e ^ 0x7fffffff);
    }
}

// ---------------- launch ----------------
extern "C" void kernel_launch(void* const* d_in, const int* in_sizes, int n_in,
                              void* d_out, int out_size)
{
    const float* vals   = (const float*)d_in[0];
    const void*  labels = d_in[1];

    const int NV = in_sizes[0];      // B * N
    const int N  = in_sizes[1];      // 200000
    const int B  = NV / N;           // 128
    const int BC = out_size;         // B * C
    const int C  = BC / B;           // 100
    int* out_enc = (int*)d_out;

    const bool fast = (C <= MAXC_FAST) && (N <= MAXN_LAB) &&
                      ((size_t)B * N == (size_t)NV);

    // Covers both output init (BC threads) and the 10k detect samples.
    int initThreads = (BC > 10240) ? BC : 10240;
    smp_init<<<(initThreads + 255) / 256, 256>>>(out_enc, BC, (const int*)labels, N);

    if (fast) {
        smp_compact<<<(N + 255) / 256, 256>>>(labels, N);

        // Single wave: <= 296 resident blocks (2 per SM at ~100KB smem each).
        const size_t smem = (size_t)C * 256 * sizeof(float);
        static int smem_set = 0;
        if (!smem_set) {
            cudaFuncSetAttribute(smp_main,
                cudaFuncAttributeMaxDynamicSharedMemorySize, 113 * 1024);
            smem_set = 1;
        }
        int rowBlocks = (B + 7) / 8;              // 16
        int S = 296 / rowBlocks;                  // 18 column slices
        if (S < 1) S = 1;
        int JW = ((N + S - 1) / S + 3) & ~3;      // quad-aligned slice width
        dim3 grid((N + JW - 1) / JW, rowBlocks);
        smp_main<<<grid, 256, smem>>>(vals, out_enc, B, N, C, JW);
    } else {
        smp_naive<<<1184, 256>>>(vals, labels, out_enc, B, N, C);
    }

    smp_fin<<<(BC + 255) / 256, 256>>>(out_enc, BC);
}